// round 2
// baseline (speedup 1.0000x reference)
#include <cuda_runtime.h>

// ---------------------------------------------------------------------------
// One-pole IIR scan:  out_t = b0*x_t + s_{t-1};  s_t = b1*x_t + a*out_t
// State-only form:    s_t = k*x_t + a*s_{t-1},   k = b1 + a*b0  (a = clamp(a1))
//
// Single fused pass: time axis split into chunks of L. Each chunk warms up
// its state from zero starting W steps before its window, where W is chosen
// ON DEVICE so that |a|^W < ~3e-14 (beyond fp32 resolution). W is clamped to
// the chunk start t0: if warmup reaches t=0 the true initial state is used,
// so the kernel is EXACT for any |a| (merely slower as |a|->1; for the
// dataset a=0.5, W=45). One read of x (+ ~18% warmup overlap), one write.
// ---------------------------------------------------------------------------

__device__ __forceinline__ float clamp_a(float a) {
    return fminf(fmaxf(a, -1.0f), 1.0f);
}

__global__ void __launch_bounds__(256)
k_fused(const float* __restrict__ x,
        const float* __restrict__ statep,
        const float* __restrict__ b0p,
        const float* __restrict__ b1p,
        const float* __restrict__ a1p,
        float* __restrict__ out,
        float* __restrict__ finalDst,   // may be null
        int T, int B, int L) {
    int c = blockIdx.x * blockDim.x + threadIdx.x;   // column (signal index)
    if (c >= B) return;
    int chunk = blockIdx.y;

    float a  = clamp_a(a1p[0]);
    float b0 = b0p[0];
    float b1 = b1p[0];
    float k  = fmaf(a, b0, b1);        // k = b1 + a*b0

    long t0   = (long)chunk * L;
    long tend = t0 + L; if (tend > T) tend = T;

    // --- warmup length: |a|^W below fp32 resolution (target 2^-45) ---
    float la = fabsf(a);
    long W;
    if (la >= 0.999999f) {
        W = t0;                         // exact: run from t=0
    } else if (la <= 1e-30f) {
        W = 2;                          // a ~ 0: one step of history suffices
    } else {
        float w = ceilf(45.0f / (-__log2f(la)));
        W = (long)w + 1;
        if (W < 2) W = 2;
    }
    if (W > t0) W = t0;

    long start = t0 - W;
    float s = (start == 0) ? statep[c] : 0.0f;

    const float* px = x + start * (long)B + c;

    // --- warmup: state-only recurrence (no stores) ---
    long nw = t0 - start;
    long i = 0;
    #pragma unroll 4
    for (; i < nw; i++) {
        float xv = px[i * (long)B];
        s = fmaf(a, s, k * xv);
    }

    // --- main: produce outputs ---
    float* po = out + t0 * (long)B + c;
    const float* pm = x + t0 * (long)B + c;
    long n = tend - t0;
    long j = 0;
    #pragma unroll 4
    for (; j < n; j++) {
        float xv = pm[j * (long)B];
        float o  = fmaf(b0, xv, s);
        po[j * (long)B] = o;
        s = fmaf(b1, xv, a * o);       // s = b1*x + a*out
    }

    // --- final state from the last chunk ---
    if (finalDst && tend == T) {
        finalDst[c] = s;
    }
}

extern "C" void kernel_launch(void* const* d_in, const int* in_sizes, int n_in,
                              void* d_out, int out_size) {
    const float* x     = (const float*)d_in[0];
    const float* state = (const float*)d_in[1];
    const float* b0    = (const float*)d_in[2];
    const float* b1    = (const float*)d_in[3];
    const float* a1    = (const float*)d_in[4];
    float* out = (float*)d_out;

    long TB = in_sizes[0];
    int  B  = in_sizes[1];
    int  T  = (int)(TB / B);

    // Chunk length along time. 256 gives 64 chunks for T=16384:
    // 64 x 4096 threads = 262k threads (~55 warps/SM) and only ~18% warmup
    // overlap at W=45.
    int L = 256;
    if (T < L) L = T;
    int numChunks = (T + L - 1) / L;

    bool writeFinal = ((long)out_size >= TB + B);
    float* finalDst = writeFinal ? (out + TB) : nullptr;

    const int TPB = 256;
    dim3 grid((B + TPB - 1) / TPB, numChunks);
    k_fused<<<grid, TPB>>>(x, state, b0, b1, a1, out, finalDst, T, B, L);
}

// round 3
// speedup vs baseline: 1.0579x; 1.0579x over previous
#include <cuda_runtime.h>

// ---------------------------------------------------------------------------
// One-pole IIR scan:  out_t = b0*x_t + s_{t-1};  s_t = b1*x_t + a*out_t
// State-only form:    s_t = k*x_t + a*s_{t-1},   k = b1 + a*b0  (a = clamp(a1))
//
// Single fused pass, chunked over time with an on-device warmup window W such
// that |a|^W < 2^-45 (below fp32 resolution); W clamps to the chunk start so
// the kernel is exact for any |a|. float2-vectorized, unroll-8 for 64 B/thread
// of memory-level parallelism; streaming stores keep the write stream out of
// L2 so warmup re-reads can hit.
// ---------------------------------------------------------------------------

__device__ __forceinline__ float clamp_a(float a) {
    return fminf(fmaxf(a, -1.0f), 1.0f);
}

__device__ __forceinline__ long warmup_len(float a, long t0) {
    float la = fabsf(a);
    long W;
    if (la >= 0.999999f) {
        W = t0;                          // exact: run from t=0
    } else if (la <= 1e-30f) {
        W = 2;
    } else {
        float w = ceilf(45.0f / (-__log2f(la)));
        W = (long)w + 1;
        if (W < 2) W = 2;
    }
    if (W > t0) W = t0;
    return W;
}

// ------------------------------ float2 path --------------------------------

__global__ void __launch_bounds__(256)
k_fused2(const float2* __restrict__ x,
         const float2* __restrict__ statep,
         const float* __restrict__ b0p,
         const float* __restrict__ b1p,
         const float* __restrict__ a1p,
         float2* __restrict__ out,
         float2* __restrict__ finalDst,   // may be null
         int T, int B2, int L) {
    int c2 = blockIdx.x * blockDim.x + threadIdx.x;
    if (c2 >= B2) return;
    int chunk = blockIdx.y;

    float a  = clamp_a(a1p[0]);
    float b0 = b0p[0];
    float b1 = b1p[0];
    float k  = fmaf(a, b0, b1);

    int t0   = chunk * L;
    int tend = t0 + L; if (tend > T) tend = T;

    long W = warmup_len(a, t0);
    int start = t0 - (int)W;

    float2 s;
    if (start == 0) {
        s = statep[c2];
    } else {
        s = make_float2(0.f, 0.f);
    }

    // --- warmup: state-only (no stores) ---
    {
        const float2* p = x + (long)start * B2 + c2;
        int nw = t0 - start;
        #pragma unroll 8
        for (int i = 0; i < nw; i++) {
            float2 xv = p[(long)i * B2];
            s.x = fmaf(a, s.x, k * xv.x);
            s.y = fmaf(a, s.y, k * xv.y);
        }
    }

    // --- main: produce outputs ---
    {
        const float2* pm = x + (long)t0 * B2 + c2;
        float2* po = out + (long)t0 * B2 + c2;
        int n = tend - t0;
        #pragma unroll 8
        for (int j = 0; j < n; j++) {
            float2 xv = pm[(long)j * B2];
            float2 o;
            o.x = fmaf(b0, xv.x, s.x);
            o.y = fmaf(b0, xv.y, s.y);
            __stcs(&po[(long)j * B2], o);          // streaming store
            s.x = fmaf(b1, xv.x, a * o.x);
            s.y = fmaf(b1, xv.y, a * o.y);
        }
    }

    if (finalDst && tend == T) {
        finalDst[c2] = s;
    }
}

// ------------------------------ scalar path --------------------------------

__global__ void __launch_bounds__(256)
k_fused1(const float* __restrict__ x,
         const float* __restrict__ statep,
         const float* __restrict__ b0p,
         const float* __restrict__ b1p,
         const float* __restrict__ a1p,
         float* __restrict__ out,
         float* __restrict__ finalDst,
         int T, int B, int L) {
    int c = blockIdx.x * blockDim.x + threadIdx.x;
    if (c >= B) return;
    int chunk = blockIdx.y;

    float a  = clamp_a(a1p[0]);
    float b0 = b0p[0];
    float b1 = b1p[0];
    float k  = fmaf(a, b0, b1);

    int t0   = chunk * L;
    int tend = t0 + L; if (tend > T) tend = T;

    long W = warmup_len(a, t0);
    int start = t0 - (int)W;
    float s = (start == 0) ? statep[c] : 0.0f;

    const float* p = x + (long)start * B + c;
    int nw = t0 - start;
    #pragma unroll 8
    for (int i = 0; i < nw; i++) {
        s = fmaf(a, s, k * p[(long)i * B]);
    }

    const float* pm = x + (long)t0 * B + c;
    float* po = out + (long)t0 * B + c;
    int n = tend - t0;
    #pragma unroll 8
    for (int j = 0; j < n; j++) {
        float xv = pm[(long)j * B];
        float o  = fmaf(b0, xv, s);
        __stcs(&po[(long)j * B], o);
        s = fmaf(b1, xv, a * o);
    }

    if (finalDst && tend == T) finalDst[c] = s;
}

// ---------------------------------------------------------------------------

extern "C" void kernel_launch(void* const* d_in, const int* in_sizes, int n_in,
                              void* d_out, int out_size) {
    const float* x     = (const float*)d_in[0];
    const float* state = (const float*)d_in[1];
    const float* b0    = (const float*)d_in[2];
    const float* b1    = (const float*)d_in[3];
    const float* a1    = (const float*)d_in[4];
    float* out = (float*)d_out;

    long TB = in_sizes[0];
    int  B  = in_sizes[1];
    int  T  = (int)(TB / B);

    int L = 256;
    if (T < L) L = T;
    int numChunks = (T + L - 1) / L;

    bool writeFinal = ((long)out_size >= TB + B);
    float* finalDst = writeFinal ? (out + TB) : nullptr;

    const int TPB = 256;

    if ((B & 1) == 0) {
        int B2 = B >> 1;
        dim3 grid((B2 + TPB - 1) / TPB, numChunks);
        k_fused2<<<grid, TPB>>>((const float2*)x, (const float2*)state,
                                b0, b1, a1, (float2*)out,
                                (float2*)finalDst, T, B2, L);
    } else {
        dim3 grid((B + TPB - 1) / TPB, numChunks);
        k_fused1<<<grid, TPB>>>(x, state, b0, b1, a1, out, finalDst, T, B, L);
    }
}